// round 1
// baseline (speedup 1.0000x reference)
#include <cuda_runtime.h>
#include <cstddef>

// Problem dims (fixed by the dataset)
#define B_DIM 16384
#define C_DIM 1000
#define D_DIM 1024
#define CPAD  1024   // padded leading dim for intermediates (float4-aligned)

// Scratch: intermediates live in device globals (no allocation allowed).
__device__ float g_xinit[(size_t)B_DIM * CPAD];  // x @ Wp^T + bp   [B, C] (ld=CPAD)
__device__ float g_out1 [(size_t)B_DIM * CPAD];  // relu(gcn1)     [B, C] (ld=CPAD)
__device__ float g_w1[C_DIM];                    // mean over heads of hw1
__device__ float g_w2[C_DIM];

// ---------------------------------------------------------------------------
// Tiny prep kernel: w[c] = mean_h hw[h, c]
// ---------------------------------------------------------------------------
__global__ void prep_w_kernel(const float* __restrict__ hw1,
                              const float* __restrict__ hw2) {
    int c = blockIdx.x * blockDim.x + threadIdx.x;
    if (c < C_DIM) {
        g_w1[c] = (hw1[c] + hw1[C_DIM + c] + hw1[2 * C_DIM + c]) * (1.0f / 3.0f);
        g_w2[c] = (hw2[c] + hw2[C_DIM + c] + hw2[2 * C_DIM + c]) * (1.0f / 3.0f);
    }
}

// ---------------------------------------------------------------------------
// Fused NT SGEMM:  C[m,n] = sum_k A[m,k] * (wscale[k]) * Bm[n,k]   (+ epilogue)
//   MODE 0: A = Aext (x, lda=D_DIM), C = g_xinit (ldc=CPAD), + bias[n]
//   MODE 1: A = g_xinit,             C = g_out1,  w = g_w1, relu
//   MODE 2: A = g_out1,              C = Cext (ldc=C_DIM),
//           w = g_w2, C = g_xinit[m,n] + 0.5 * acc
// Tiles: BM=BN=128, BK=8, 256 threads, 8x8 per-thread microtile.
// Requirements satisfied by the shapes: K % 8 == 0 (1024, 1000),
// M % 128 == 0; only N (=1000) needs a partial last tile.
// ---------------------------------------------------------------------------
template <int MODE>
__global__ void __launch_bounds__(256, 2)
gemm_nt_kernel(const float* __restrict__ Aext,
               const float* __restrict__ Bm, int ldb,
               const float* __restrict__ bias,
               float* __restrict__ Cext,
               int M, int N, int K) {
    constexpr int BM = 128, BN = 128, BK = 8;

    const float* A;
    const float* w = nullptr;
    float* Cp;
    int lda, ldc;
    if (MODE == 0) { A = Aext;    lda = D_DIM; Cp = g_xinit; ldc = CPAD;  }
    if (MODE == 1) { A = g_xinit; lda = CPAD;  Cp = g_out1;  ldc = CPAD;  w = g_w1; }
    if (MODE == 2) { A = g_out1;  lda = CPAD;  Cp = Cext;    ldc = C_DIM; w = g_w2; }

    __shared__ float As[BK][BM];
    __shared__ float Bs[BK][BN];

    const int tid = threadIdx.x;
    const int m0 = blockIdx.y * BM;
    const int n0 = blockIdx.x * BN;
    const int tx = tid & 15;   // 0..15 -> N direction (8 cols each)
    const int ty = tid >> 4;   // 0..15 -> M direction (8 rows each)

    // Loader mapping: 2 threads per tile-row, each loads a float4 of K.
    const int lr = tid >> 1;          // 0..127 : row within tile
    const int lk = (tid & 1) * 4;     // 0 or 4 : K offset of the float4

    const float* Aptr = A + (size_t)(m0 + lr) * lda + lk;
    const int bn = n0 + lr;
    const bool bvalid = (bn < N);
    const float* Bptr = bvalid ? (Bm + (size_t)bn * ldb + lk) : Bm;

    float acc[8][8];
#pragma unroll
    for (int i = 0; i < 8; i++)
#pragma unroll
        for (int j = 0; j < 8; j++) acc[i][j] = 0.0f;

    for (int k0 = 0; k0 < K; k0 += BK) {
        // --- stage tiles ---
        float4 av = *reinterpret_cast<const float4*>(Aptr + k0);
        float4 bv = make_float4(0.f, 0.f, 0.f, 0.f);
        if (bvalid) bv = *reinterpret_cast<const float4*>(Bptr + k0);
        if (MODE != 0) {
            // fold per-K head-weight into the B tile
            bv.x *= w[k0 + lk + 0];
            bv.y *= w[k0 + lk + 1];
            bv.z *= w[k0 + lk + 2];
            bv.w *= w[k0 + lk + 3];
        }
        As[lk + 0][lr] = av.x;
        As[lk + 1][lr] = av.y;
        As[lk + 2][lr] = av.z;
        As[lk + 3][lr] = av.w;
        Bs[lk + 0][lr] = bv.x;
        Bs[lk + 1][lr] = bv.y;
        Bs[lk + 2][lr] = bv.z;
        Bs[lk + 3][lr] = bv.w;
        __syncthreads();

        // --- compute ---
#pragma unroll
        for (int kk = 0; kk < BK; kk++) {
            float af[8], bf[8];
            *reinterpret_cast<float4*>(&af[0]) =
                *reinterpret_cast<const float4*>(&As[kk][ty * 8]);
            *reinterpret_cast<float4*>(&af[4]) =
                *reinterpret_cast<const float4*>(&As[kk][ty * 8 + 4]);
            *reinterpret_cast<float4*>(&bf[0]) =
                *reinterpret_cast<const float4*>(&Bs[kk][tx * 8]);
            *reinterpret_cast<float4*>(&bf[4]) =
                *reinterpret_cast<const float4*>(&Bs[kk][tx * 8 + 4]);
#pragma unroll
            for (int i = 0; i < 8; i++)
#pragma unroll
                for (int j = 0; j < 8; j++)
                    acc[i][j] = fmaf(af[i], bf[j], acc[i][j]);
        }
        __syncthreads();
    }

    // --- epilogue ---
#pragma unroll
    for (int i = 0; i < 8; i++) {
        const int m = m0 + ty * 8 + i;
#pragma unroll
        for (int j = 0; j < 8; j++) {
            const int n = n0 + tx * 8 + j;
            if (n < N) {
                float v = acc[i][j];
                if (MODE == 0) v += bias[n];
                if (MODE == 1) v = fmaxf(v, 0.0f);
                if (MODE == 2) v = g_xinit[(size_t)m * CPAD + n] + 0.5f * v;
                Cp[(size_t)m * ldc + n] = v;
            }
        }
    }
}

// ---------------------------------------------------------------------------
// Launch: inputs per metadata order: x, adj, Wp, bp, hw1, hw2
// ---------------------------------------------------------------------------
extern "C" void kernel_launch(void* const* d_in, const int* in_sizes, int n_in,
                              void* d_out, int out_size) {
    const float* x   = (const float*)d_in[0];  // [B, D]
    const float* adj = (const float*)d_in[1];  // [C, C]
    const float* Wp  = (const float*)d_in[2];  // [C, D]
    const float* bp  = (const float*)d_in[3];  // [C]
    const float* hw1 = (const float*)d_in[4];  // [H, C]
    const float* hw2 = (const float*)d_in[5];  // [H, C]
    float* out = (float*)d_out;                // [B, C]

    prep_w_kernel<<<(C_DIM + 255) / 256, 256>>>(hw1, hw2);

    dim3 block(256);
    dim3 grid((C_DIM + 127) / 128, B_DIM / 128);  // (8, 128)

    // 1) x_init = x @ Wp^T + bp
    gemm_nt_kernel<0><<<grid, block>>>(x, Wp, D_DIM, bp, nullptr,
                                       B_DIM, C_DIM, D_DIM);
    // 2) out1 = relu((x_init * w1) @ adj^T)
    gemm_nt_kernel<1><<<grid, block>>>(nullptr, adj, C_DIM, nullptr, nullptr,
                                       B_DIM, C_DIM, C_DIM);
    // 3) out = x_init + 0.5 * ((out1 * w2) @ adj^T)
    gemm_nt_kernel<2><<<grid, block>>>(nullptr, adj, C_DIM, nullptr, out,
                                       B_DIM, C_DIM, C_DIM);
}

// round 4
// speedup vs baseline: 3.6062x; 3.6062x over previous
#include <cuda_runtime.h>
#include <cstdint>
#include <cstddef>

// ---------------------------------------------------------------------------
// Problem dims (fixed by the dataset)
// ---------------------------------------------------------------------------
#define B_DIM 16384
#define C_DIM 1000
#define D_DIM 1024
#define CPAD  1024   // padded K / leading dim everywhere

// GEMM tiling
#define BM 128
#define BN 128
#define BK 32
#define KT (CPAD / BK)     // 32
#define STAGES 4
#define NTH 256

#define LDSTR 36                               // smem row stride (floats), conflict-free
#define TILE_FLOATS (128 * LDSTR)              // one operand tile
#define STAGE_FLOATS (2 * TILE_FLOATS)
#define SMEM_BYTES (STAGES * STAGE_FLOATS * 4) // 147456

// ---------------------------------------------------------------------------
// Device scratch (no allocation allowed). Zero-initialized at load; padding
// columns [1000,1024) of intermediates are never written -> stay 0.
// ---------------------------------------------------------------------------
__device__ float g_xrnd [(size_t)B_DIM * CPAD];   // tf32-rounded x
__device__ float g_wp   [(size_t)C_DIM * CPAD];   // tf32-rounded Wp
__device__ float g_adj1 [(size_t)C_DIM * CPAD];   // rn(adj[c,k] * w1[k]), k-padded
__device__ float g_adj2 [(size_t)C_DIM * CPAD];
__device__ float g_xinit[(size_t)B_DIM * CPAD];   // tf32-rounded x@Wp^T+bp
__device__ float g_out1 [(size_t)B_DIM * CPAD];   // tf32-rounded relu(gcn1)

// ---------------------------------------------------------------------------
// PTX helpers (all sm_80/sm_90-era — compile for plain sm_100)
// ---------------------------------------------------------------------------
__device__ __forceinline__ uint32_t su32(const void* p) {
    uint32_t a;
    asm("{ .reg .u64 t; cvta.to.shared.u64 t, %1; cvt.u32.u64 %0, t; }"
        : "=r"(a) : "l"(p));
    return a;
}
__device__ __forceinline__ float rn_tf32(float x) {
    uint32_t r;
    asm("cvt.rn.tf32.f32 %0, %1;" : "=r"(r) : "f"(x));
    return __uint_as_float(r);
}
__device__ __forceinline__ void cpasync16(uint32_t dst, const void* src) {
    asm volatile("cp.async.cg.shared.global [%0], [%1], 16;"
                 :: "r"(dst), "l"(src));
}
// zero-fill variant: src-size 0 -> 16 bytes of zeros written
__device__ __forceinline__ void cpasync16z(uint32_t dst, const void* src,
                                           bool valid) {
    int sz = valid ? 16 : 0;
    asm volatile("cp.async.cg.shared.global [%0], [%1], 16, %2;"
                 :: "r"(dst), "l"(src), "r"(sz));
}
#define CP_COMMIT() asm volatile("cp.async.commit_group;")
#define CP_WAIT(n)  asm volatile("cp.async.wait_group %0;" :: "n"(n))

__device__ __forceinline__ void mma16n8k8(float* c, const uint32_t* a,
                                          const uint32_t* b) {
    asm volatile(
        "mma.sync.aligned.m16n8k8.row.col.f32.tf32.tf32.f32 "
        "{%0,%1,%2,%3}, {%4,%5,%6,%7}, {%8,%9}, {%0,%1,%2,%3};\n"
        : "+f"(c[0]), "+f"(c[1]), "+f"(c[2]), "+f"(c[3])
        : "r"(a[0]), "r"(a[1]), "r"(a[2]), "r"(a[3]), "r"(b[0]), "r"(b[1]));
}

// ---------------------------------------------------------------------------
// Prep kernels
// ---------------------------------------------------------------------------
__global__ void round_copy_kernel(const float* __restrict__ src,
                                  float* __restrict__ dst, int n4) {
    int i = blockIdx.x * blockDim.x + threadIdx.x;
    if (i < n4) {
        float4 v = reinterpret_cast<const float4*>(src)[i];
        v.x = rn_tf32(v.x); v.y = rn_tf32(v.y);
        v.z = rn_tf32(v.z); v.w = rn_tf32(v.w);
        reinterpret_cast<float4*>(dst)[i] = v;
    }
}

__global__ void prep_adj_kernel(const float* __restrict__ adj,
                                const float* __restrict__ hw1,
                                const float* __restrict__ hw2) {
    int k = blockIdx.x * blockDim.x + threadIdx.x;   // 0..1023
    int c = blockIdx.y;                              // 0..999
    float a1 = 0.f, a2 = 0.f;
    if (k < C_DIM) {
        float av = adj[(size_t)c * C_DIM + k];
        float w1 = (hw1[k] + hw1[C_DIM + k] + hw1[2 * C_DIM + k]) * (1.f / 3.f);
        float w2 = (hw2[k] + hw2[C_DIM + k] + hw2[2 * C_DIM + k]) * (1.f / 3.f);
        a1 = rn_tf32(av * w1);
        a2 = rn_tf32(av * w2);
    }
    g_adj1[(size_t)c * CPAD + k] = a1;
    g_adj2[(size_t)c * CPAD + k] = a2;
}

// ---------------------------------------------------------------------------
// Fused tf32 mma.sync GEMM:  D[m,n] = sum_k A[m,k] * B[n,k]
//   MODE 0: +bias, round->Cout (ld CPAD)
//   MODE 1: relu, round->Cout  (ld CPAD)
//   MODE 2: Cout = resid + 0.5*acc (ld C_DIM, final output)
// lda = ldb = CPAD for all modes, K = CPAD.
// ---------------------------------------------------------------------------
__device__ __forceinline__ void load_tile(
    uint32_t sm0, const float* __restrict__ A, const float* __restrict__ Bm,
    int m0, int n0, int kt, int tid)
{
    const int slot = kt % STAGES;
    const uint32_t sA = sm0 + slot * (STAGE_FLOATS * 4);
    const uint32_t sB = sA + TILE_FLOATS * 4;
    const int k0 = kt * BK;
    const int r  = tid >> 3;          // 0..31
    const int kl = (tid & 7) * 4;     // 0,4,...,28

#pragma unroll
    for (int p = 0; p < 4; p++) {
        const int row = p * 32 + r;
        cpasync16(sA + (uint32_t)(row * LDSTR + kl) * 4,
                  A + (size_t)(m0 + row) * CPAD + k0 + kl);
    }
#pragma unroll
    for (int p = 0; p < 4; p++) {
        const int row = p * 32 + r;
        const int n = n0 + row;
        const int nc = (n < C_DIM) ? n : (C_DIM - 1);   // clamp src addr
        cpasync16z(sB + (uint32_t)(row * LDSTR + kl) * 4,
                   Bm + (size_t)nc * CPAD + k0 + kl, n < C_DIM);
    }
}

template <int MODE>
__global__ void __launch_bounds__(NTH, 1)
gemm_tc(const float* __restrict__ A, const float* __restrict__ Bm,
        const float* __restrict__ bias, const float* __restrict__ resid,
        float* __restrict__ Cout)
{
    extern __shared__ float smem[];
    const uint32_t sm0 = su32(smem);

    const int tid  = threadIdx.x;
    const int warp = tid >> 5;
    const int lane = tid & 31;
    const int g = lane >> 2;          // groupID 0..7
    const int t = lane & 3;           // thread-in-group 0..3
    const int wm = (warp >> 2) * 64;  // warp M offset (0 or 64)
    const int wn = (warp & 3) * 32;   // warp N offset (0,32,64,96)

    const int m0 = blockIdx.y * BM;
    const int n0 = blockIdx.x * BN;

    float acc[4][4][4];
#pragma unroll
    for (int i = 0; i < 4; i++)
#pragma unroll
        for (int j = 0; j < 4; j++)
#pragma unroll
            for (int c = 0; c < 4; c++) acc[i][j][c] = 0.f;

    // prologue: fill STAGES-1 stages
#pragma unroll
    for (int kt = 0; kt < STAGES - 1; kt++) {
        load_tile(sm0, A, Bm, m0, n0, kt, tid);
        CP_COMMIT();
    }

    for (int kt = 0; kt < KT; kt++) {
        CP_WAIT(STAGES - 2);
        __syncthreads();

        const int kn = kt + STAGES - 1;
        if (kn < KT) load_tile(sm0, A, Bm, m0, n0, kn, tid);
        CP_COMMIT();

        const int slot = kt % STAGES;
        const float* sA = smem + slot * STAGE_FLOATS;
        const float* sB = sA + TILE_FLOATS;

#pragma unroll
        for (int ks = 0; ks < 4; ks++) {
            const int kk = ks * 8;
            uint32_t a[4][4], b[4][2];
#pragma unroll
            for (int i = 0; i < 4; i++) {
                const float* p = sA + (wm + i * 16 + g) * LDSTR + kk + t;
                a[i][0] = __float_as_uint(p[0]);
                a[i][1] = __float_as_uint(p[8 * LDSTR]);
                a[i][2] = __float_as_uint(p[4]);
                a[i][3] = __float_as_uint(p[8 * LDSTR + 4]);
            }
#pragma unroll
            for (int j = 0; j < 4; j++) {
                const float* p = sB + (wn + j * 8 + g) * LDSTR + kk + t;
                b[j][0] = __float_as_uint(p[0]);
                b[j][1] = __float_as_uint(p[4]);
            }
#pragma unroll
            for (int i = 0; i < 4; i++)
#pragma unroll
                for (int j = 0; j < 4; j++)
                    mma16n8k8(acc[i][j], a[i], b[j]);
        }
    }

    // epilogue: per-thread float2 stores
#pragma unroll
    for (int i = 0; i < 4; i++) {
        const int mr0 = m0 + wm + i * 16 + g;       // rows mr0 and mr0+8
#pragma unroll
        for (int j = 0; j < 4; j++) {
            const int n = n0 + wn + j * 8 + t * 2;
            if (n < C_DIM) {
                float c0 = acc[i][j][0], c1 = acc[i][j][1];
                float c2 = acc[i][j][2], c3 = acc[i][j][3];
                if (MODE == 0) {
                    const float b0 = bias[n], b1 = bias[n + 1];
                    c0 = rn_tf32(c0 + b0); c1 = rn_tf32(c1 + b1);
                    c2 = rn_tf32(c2 + b0); c3 = rn_tf32(c3 + b1);
                } else if (MODE == 1) {
                    c0 = rn_tf32(fmaxf(c0, 0.f)); c1 = rn_tf32(fmaxf(c1, 0.f));
                    c2 = rn_tf32(fmaxf(c2, 0.f)); c3 = rn_tf32(fmaxf(c3, 0.f));
                }
                if (MODE == 2) {
                    float2 r0 = *reinterpret_cast<const float2*>(
                        resid + (size_t)mr0 * CPAD + n);
                    float2 r1 = *reinterpret_cast<const float2*>(
                        resid + (size_t)(mr0 + 8) * CPAD + n);
                    float2 v0 = make_float2(r0.x + 0.5f * c0, r0.y + 0.5f * c1);
                    float2 v1 = make_float2(r1.x + 0.5f * c2, r1.y + 0.5f * c3);
                    *reinterpret_cast<float2*>(
                        Cout + (size_t)mr0 * C_DIM + n) = v0;
                    *reinterpret_cast<float2*>(
                        Cout + (size_t)(mr0 + 8) * C_DIM + n) = v1;
                } else {
                    *reinterpret_cast<float2*>(
                        Cout + (size_t)mr0 * CPAD + n) = make_float2(c0, c1);
                    *reinterpret_cast<float2*>(
                        Cout + (size_t)(mr0 + 8) * CPAD + n) = make_float2(c2, c3);
                }
            }
        }
    }
}

// ---------------------------------------------------------------------------
// Launch: inputs per metadata order: x, adj, Wp, bp, hw1, hw2
// ---------------------------------------------------------------------------
extern "C" void kernel_launch(void* const* d_in, const int* in_sizes, int n_in,
                              void* d_out, int out_size) {
    const float* x   = (const float*)d_in[0];
    const float* adj = (const float*)d_in[1];
    const float* Wp  = (const float*)d_in[2];
    const float* bp  = (const float*)d_in[3];
    const float* hw1 = (const float*)d_in[4];
    const float* hw2 = (const float*)d_in[5];
    float* out = (float*)d_out;

    float *p_xrnd, *p_wp, *p_adj1, *p_adj2, *p_xinit, *p_out1;
    cudaGetSymbolAddress((void**)&p_xrnd,  g_xrnd);
    cudaGetSymbolAddress((void**)&p_wp,    g_wp);
    cudaGetSymbolAddress((void**)&p_adj1,  g_adj1);
    cudaGetSymbolAddress((void**)&p_adj2,  g_adj2);
    cudaGetSymbolAddress((void**)&p_xinit, g_xinit);
    cudaGetSymbolAddress((void**)&p_out1,  g_out1);

    cudaFuncSetAttribute(gemm_tc<0>,
        cudaFuncAttributeMaxDynamicSharedMemorySize, SMEM_BYTES);
    cudaFuncSetAttribute(gemm_tc<1>,
        cudaFuncAttributeMaxDynamicSharedMemorySize, SMEM_BYTES);
    cudaFuncSetAttribute(gemm_tc<2>,
        cudaFuncAttributeMaxDynamicSharedMemorySize, SMEM_BYTES);

    // prep: tf32-round x, Wp; prescale+round adj by head means
    {
        int n4 = (B_DIM * D_DIM) / 4;
        round_copy_kernel<<<(n4 + 255) / 256, 256>>>(x, p_xrnd, n4);
        int w4 = (C_DIM * D_DIM) / 4;
        round_copy_kernel<<<(w4 + 255) / 256, 256>>>(Wp, p_wp, w4);
        dim3 g(CPAD / 256, C_DIM);
        prep_adj_kernel<<<g, 256>>>(adj, hw1, hw2);
    }

    dim3 grid((C_DIM + BN - 1) / BN, B_DIM / BM);  // (8, 128)
    dim3 block(NTH);

    gemm_tc<0><<<grid, block, SMEM_BYTES>>>(p_xrnd, p_wp, bp, nullptr, p_xinit);
    gemm_tc<1><<<grid, block, SMEM_BYTES>>>(p_xinit, p_adj1, nullptr, nullptr, p_out1);
    gemm_tc<2><<<grid, block, SMEM_BYTES>>>(p_out1, p_adj2, nullptr, p_xinit, out);
}

// round 5
// speedup vs baseline: 4.0148x; 1.1133x over previous
#include <cuda_runtime.h>
#include <cstdint>
#include <cstddef>

// ---------------------------------------------------------------------------
// Problem dims (fixed by the dataset)
// ---------------------------------------------------------------------------
#define B_DIM 16384
#define C_DIM 1000
#define D_DIM 1024
#define CPAD  1024   // padded K / leading dim everywhere

// GEMM tiling
#define BM 128
#define BN 128
#define BK 32
#define KT (CPAD / BK)     // 32
#define STAGES 3
#define NTH 256

#define LDSTR 36                               // smem row stride (floats), conflict-free
#define TILE_FLOATS (128 * LDSTR)              // one operand tile
#define STAGE_FLOATS (2 * TILE_FLOATS)
#define SMEM_BYTES (STAGES * STAGE_FLOATS * 4) // 110592 -> 2 CTAs/SM

// ---------------------------------------------------------------------------
// Device scratch (no allocation allowed). Zero-initialized at load; padding
// columns [1000,1024) of intermediates are never written -> stay 0.
// ---------------------------------------------------------------------------
__device__ float g_xrnd [(size_t)B_DIM * CPAD];   // tf32-rounded x
__device__ float g_wp   [(size_t)C_DIM * CPAD];   // tf32-rounded Wp
__device__ float g_adj1 [(size_t)C_DIM * CPAD];   // rn(adj[c,k] * w1[k]), k-padded
__device__ float g_adj2 [(size_t)C_DIM * CPAD];
__device__ float g_xinit[(size_t)B_DIM * CPAD];   // tf32-rounded x@Wp^T+bp
__device__ float g_out1 [(size_t)B_DIM * CPAD];   // tf32-rounded relu(gcn1)

// ---------------------------------------------------------------------------
// PTX helpers (all sm_80/sm_90-era — compile for plain sm_100)
// ---------------------------------------------------------------------------
__device__ __forceinline__ uint32_t su32(const void* p) {
    uint32_t a;
    asm("{ .reg .u64 t; cvta.to.shared.u64 t, %1; cvt.u32.u64 %0, t; }"
        : "=r"(a) : "l"(p));
    return a;
}
__device__ __forceinline__ float rn_tf32(float x) {
    uint32_t r;
    asm("cvt.rn.tf32.f32 %0, %1;" : "=r"(r) : "f"(x));
    return __uint_as_float(r);
}
__device__ __forceinline__ void cpasync16(uint32_t dst, const void* src) {
    asm volatile("cp.async.cg.shared.global [%0], [%1], 16;"
                 :: "r"(dst), "l"(src));
}
// zero-fill variant: src-size 0 -> 16 bytes of zeros written
__device__ __forceinline__ void cpasync16z(uint32_t dst, const void* src,
                                           bool valid) {
    int sz = valid ? 16 : 0;
    asm volatile("cp.async.cg.shared.global [%0], [%1], 16, %2;"
                 :: "r"(dst), "l"(src), "r"(sz));
}
#define CP_COMMIT() asm volatile("cp.async.commit_group;")
#define CP_WAIT(n)  asm volatile("cp.async.wait_group %0;" :: "n"(n))

__device__ __forceinline__ void mma16n8k8(float* c, const uint32_t* a,
                                          const uint32_t* b) {
    asm volatile(
        "mma.sync.aligned.m16n8k8.row.col.f32.tf32.tf32.f32 "
        "{%0,%1,%2,%3}, {%4,%5,%6,%7}, {%8,%9}, {%0,%1,%2,%3};\n"
        : "+f"(c[0]), "+f"(c[1]), "+f"(c[2]), "+f"(c[3])
        : "r"(a[0]), "r"(a[1]), "r"(a[2]), "r"(a[3]), "r"(b[0]), "r"(b[1]));
}

// ---------------------------------------------------------------------------
// Prep kernels
// ---------------------------------------------------------------------------
__global__ void round_copy_kernel(const float* __restrict__ src,
                                  float* __restrict__ dst, int n4) {
    int i = blockIdx.x * blockDim.x + threadIdx.x;
    if (i < n4) {
        float4 v = reinterpret_cast<const float4*>(src)[i];
        v.x = rn_tf32(v.x); v.y = rn_tf32(v.y);
        v.z = rn_tf32(v.z); v.w = rn_tf32(v.w);
        reinterpret_cast<float4*>(dst)[i] = v;
    }
}

__global__ void prep_adj_kernel(const float* __restrict__ adj,
                                const float* __restrict__ hw1,
                                const float* __restrict__ hw2) {
    int k = blockIdx.x * blockDim.x + threadIdx.x;   // 0..1023
    int c = blockIdx.y;                              // 0..999
    float a1 = 0.f, a2 = 0.f;
    if (k < C_DIM) {
        float av = adj[(size_t)c * C_DIM + k];
        float w1 = (hw1[k] + hw1[C_DIM + k] + hw1[2 * C_DIM + k]) * (1.f / 3.f);
        float w2 = (hw2[k] + hw2[C_DIM + k] + hw2[2 * C_DIM + k]) * (1.f / 3.f);
        a1 = rn_tf32(av * w1);
        a2 = rn_tf32(av * w2);
    }
    g_adj1[(size_t)c * CPAD + k] = a1;
    g_adj2[(size_t)c * CPAD + k] = a2;
}

// ---------------------------------------------------------------------------
// Fused tf32 mma.sync GEMM:  D[m,n] = sum_k A[m,k] * B[n,k]
//   MODE 0: +bias, round->Cout (ld CPAD)
//   MODE 1: relu, round->Cout  (ld CPAD)
//   MODE 2: Cout = resid + 0.5*acc (ld C_DIM, final output)
// lda = ldb = CPAD for all modes, K = CPAD.
// ---------------------------------------------------------------------------
__device__ __forceinline__ void load_tile(
    uint32_t sm0, const float* __restrict__ A, const float* __restrict__ Bm,
    int m0, int n0, int kt, int tid)
{
    const int slot = kt % STAGES;
    const uint32_t sA = sm0 + slot * (STAGE_FLOATS * 4);
    const uint32_t sB = sA + TILE_FLOATS * 4;
    const int k0 = kt * BK;
    const int r  = tid >> 3;          // 0..31
    const int kl = (tid & 7) * 4;     // 0,4,...,28

#pragma unroll
    for (int p = 0; p < 4; p++) {
        const int row = p * 32 + r;
        cpasync16(sA + (uint32_t)(row * LDSTR + kl) * 4,
                  A + (size_t)(m0 + row) * CPAD + k0 + kl);
    }
#pragma unroll
    for (int p = 0; p < 4; p++) {
        const int row = p * 32 + r;
        const int n = n0 + row;
        const int nc = (n < C_DIM) ? n : (C_DIM - 1);   // clamp src addr
        cpasync16z(sB + (uint32_t)(row * LDSTR + kl) * 4,
                   Bm + (size_t)nc * CPAD + k0 + kl, n < C_DIM);
    }
}

template <int MODE>
__global__ void __launch_bounds__(NTH, 2)
gemm_tc(const float* __restrict__ A, const float* __restrict__ Bm,
        const float* __restrict__ bias, const float* __restrict__ resid,
        float* __restrict__ Cout)
{
    extern __shared__ float smem[];
    const uint32_t sm0 = su32(smem);

    const int tid  = threadIdx.x;
    const int warp = tid >> 5;
    const int lane = tid & 31;
    const int g = lane >> 2;          // groupID 0..7
    const int t = lane & 3;           // thread-in-group 0..3
    const int wm = (warp >> 2) * 64;  // warp M offset (0 or 64)
    const int wn = (warp & 3) * 32;   // warp N offset (0,32,64,96)

    const int m0 = blockIdx.y * BM;
    const int n0 = blockIdx.x * BN;

    float acc[4][4][4];
#pragma unroll
    for (int i = 0; i < 4; i++)
#pragma unroll
        for (int j = 0; j < 4; j++)
#pragma unroll
            for (int c = 0; c < 4; c++) acc[i][j][c] = 0.f;

    // prologue: fill STAGES-1 stages
#pragma unroll
    for (int kt = 0; kt < STAGES - 1; kt++) {
        load_tile(sm0, A, Bm, m0, n0, kt, tid);
        CP_COMMIT();
    }

    for (int kt = 0; kt < KT; kt++) {
        CP_WAIT(STAGES - 2);
        __syncthreads();

        const int kn = kt + STAGES - 1;
        if (kn < KT) load_tile(sm0, A, Bm, m0, n0, kn, tid);
        CP_COMMIT();

        const int slot = kt % STAGES;
        const float* sA = smem + slot * STAGE_FLOATS;
        const float* sB = sA + TILE_FLOATS;

#pragma unroll
        for (int ks = 0; ks < 4; ks++) {
            const int kk = ks * 8;
            uint32_t a[4][4], b[4][2];
#pragma unroll
            for (int i = 0; i < 4; i++) {
                const float* p = sA + (wm + i * 16 + g) * LDSTR + kk + t;
                a[i][0] = __float_as_uint(p[0]);
                a[i][1] = __float_as_uint(p[8 * LDSTR]);
                a[i][2] = __float_as_uint(p[4]);
                a[i][3] = __float_as_uint(p[8 * LDSTR + 4]);
            }
#pragma unroll
            for (int j = 0; j < 4; j++) {
                const float* p = sB + (wn + j * 8 + g) * LDSTR + kk + t;
                b[j][0] = __float_as_uint(p[0]);
                b[j][1] = __float_as_uint(p[4]);
            }
#pragma unroll
            for (int i = 0; i < 4; i++)
#pragma unroll
                for (int j = 0; j < 4; j++)
                    mma16n8k8(acc[i][j], a[i], b[j]);
        }
    }

    // epilogue: per-thread float2 stores
#pragma unroll
    for (int i = 0; i < 4; i++) {
        const int mr0 = m0 + wm + i * 16 + g;       // rows mr0 and mr0+8
#pragma unroll
        for (int j = 0; j < 4; j++) {
            const int n = n0 + wn + j * 8 + t * 2;
            if (n < C_DIM) {
                float c0 = acc[i][j][0], c1 = acc[i][j][1];
                float c2 = acc[i][j][2], c3 = acc[i][j][3];
                if (MODE == 0) {
                    const float b0 = bias[n], b1 = bias[n + 1];
                    c0 = rn_tf32(c0 + b0); c1 = rn_tf32(c1 + b1);
                    c2 = rn_tf32(c2 + b0); c3 = rn_tf32(c3 + b1);
                } else if (MODE == 1) {
                    c0 = rn_tf32(fmaxf(c0, 0.f)); c1 = rn_tf32(fmaxf(c1, 0.f));
                    c2 = rn_tf32(fmaxf(c2, 0.f)); c3 = rn_tf32(fmaxf(c3, 0.f));
                }
                if (MODE == 2) {
                    float2 r0 = *reinterpret_cast<const float2*>(
                        resid + (size_t)mr0 * CPAD + n);
                    float2 r1 = *reinterpret_cast<const float2*>(
                        resid + (size_t)(mr0 + 8) * CPAD + n);
                    float2 v0 = make_float2(r0.x + 0.5f * c0, r0.y + 0.5f * c1);
                    float2 v1 = make_float2(r1.x + 0.5f * c2, r1.y + 0.5f * c3);
                    *reinterpret_cast<float2*>(
                        Cout + (size_t)mr0 * C_DIM + n) = v0;
                    *reinterpret_cast<float2*>(
                        Cout + (size_t)(mr0 + 8) * C_DIM + n) = v1;
                } else {
                    *reinterpret_cast<float2*>(
                        Cout + (size_t)mr0 * CPAD + n) = make_float2(c0, c1);
                    *reinterpret_cast<float2*>(
                        Cout + (size_t)(mr0 + 8) * CPAD + n) = make_float2(c2, c3);
                }
            }
        }
    }
}

// ---------------------------------------------------------------------------
// Launch: inputs per metadata order: x, adj, Wp, bp, hw1, hw2
// ---------------------------------------------------------------------------
extern "C" void kernel_launch(void* const* d_in, const int* in_sizes, int n_in,
                              void* d_out, int out_size) {
    const float* x   = (const float*)d_in[0];
    const float* adj = (const float*)d_in[1];
    const float* Wp  = (const float*)d_in[2];
    const float* bp  = (const float*)d_in[3];
    const float* hw1 = (const float*)d_in[4];
    const float* hw2 = (const float*)d_in[5];
    float* out = (float*)d_out;

    float *p_xrnd, *p_wp, *p_adj1, *p_adj2, *p_xinit, *p_out1;
    cudaGetSymbolAddress((void**)&p_xrnd,  g_xrnd);
    cudaGetSymbolAddress((void**)&p_wp,    g_wp);
    cudaGetSymbolAddress((void**)&p_adj1,  g_adj1);
    cudaGetSymbolAddress((void**)&p_adj2,  g_adj2);
    cudaGetSymbolAddress((void**)&p_xinit, g_xinit);
    cudaGetSymbolAddress((void**)&p_out1,  g_out1);

    cudaFuncSetAttribute(gemm_tc<0>,
        cudaFuncAttributeMaxDynamicSharedMemorySize, SMEM_BYTES);
    cudaFuncSetAttribute(gemm_tc<1>,
        cudaFuncAttributeMaxDynamicSharedMemorySize, SMEM_BYTES);
    cudaFuncSetAttribute(gemm_tc<2>,
        cudaFuncAttributeMaxDynamicSharedMemorySize, SMEM_BYTES);

    // prep: tf32-round x, Wp; prescale+round adj by head means
    {
        int n4 = (B_DIM * D_DIM) / 4;
        round_copy_kernel<<<(n4 + 255) / 256, 256>>>(x, p_xrnd, n4);
        int w4 = (C_DIM * D_DIM) / 4;
        round_copy_kernel<<<(w4 + 255) / 256, 256>>>(Wp, p_wp, w4);
        dim3 g(CPAD / 256, C_DIM);
        prep_adj_kernel<<<g, 256>>>(adj, hw1, hw2);
    }

    dim3 grid((C_DIM + BN - 1) / BN, B_DIM / BM);  // (8, 128)
    dim3 block(NTH);

    gemm_tc<0><<<grid, block, SMEM_BYTES>>>(p_xrnd, p_wp, bp, nullptr, p_xinit);
    gemm_tc<1><<<grid, block, SMEM_BYTES>>>(p_xinit, p_adj1, nullptr, nullptr, p_out1);
    gemm_tc<2><<<grid, block, SMEM_BYTES>>>(p_out1, p_adj2, nullptr, p_xinit, out);
}

// round 6
// speedup vs baseline: 4.4063x; 1.0975x over previous
#include <cuda_runtime.h>
#include <cstdint>
#include <cstddef>

// ---------------------------------------------------------------------------
// Problem dims (fixed by the dataset)
// ---------------------------------------------------------------------------
#define B_DIM 16384
#define C_DIM 1000
#define D_DIM 1024
#define CPAD  1024   // padded K / leading dim everywhere

// GEMM tiling
#define BM 128
#define BN 128
#define BK 32
#define KT (CPAD / BK)     // 32
#define STAGES 3
#define NTH 256

#define LDSTR 36                               // smem row stride (floats)
// 144B row stride => ldmatrix's 8 rows land on 8 distinct 16B banks: conflict-free
#define TILE_FLOATS (128 * LDSTR)              // one operand tile
#define STAGE_FLOATS (2 * TILE_FLOATS)
#define STAGE_BYTES (STAGE_FLOATS * 4)
#define SMEM_BYTES (STAGES * STAGE_BYTES)      // 110592 -> 2 CTAs/SM

// ---------------------------------------------------------------------------
// Device scratch (no allocation allowed). Zero-initialized at load; padding
// columns [1000,1024) of intermediates are never written -> stay 0.
// ---------------------------------------------------------------------------
__device__ float g_xrnd [(size_t)B_DIM * CPAD];   // tf32-rounded x
__device__ float g_wp   [(size_t)C_DIM * CPAD];   // tf32-rounded Wp
__device__ float g_adj1 [(size_t)C_DIM * CPAD];   // rn(adj[c,k] * w1[k]), k-padded
__device__ float g_adj2 [(size_t)C_DIM * CPAD];
__device__ float g_xinit[(size_t)B_DIM * CPAD];   // tf32-rounded x@Wp^T+bp
__device__ float g_out1 [(size_t)B_DIM * CPAD];   // tf32-rounded relu(gcn1)

// ---------------------------------------------------------------------------
// PTX helpers (all sm_80/sm_90-era — compile for plain sm_100)
// ---------------------------------------------------------------------------
__device__ __forceinline__ uint32_t su32(const void* p) {
    uint32_t a;
    asm("{ .reg .u64 t; cvta.to.shared.u64 t, %1; cvt.u32.u64 %0, t; }"
        : "=r"(a) : "l"(p));
    return a;
}
__device__ __forceinline__ float rn_tf32(float x) {
    uint32_t r;
    asm("cvt.rn.tf32.f32 %0, %1;" : "=r"(r) : "f"(x));
    return __uint_as_float(r);
}
__device__ __forceinline__ void cpasync16(uint32_t dst, const void* src) {
    asm volatile("cp.async.cg.shared.global [%0], [%1], 16;"
                 :: "r"(dst), "l"(src));
}
// zero-fill variant: src-size 0 -> 16 bytes of zeros written
__device__ __forceinline__ void cpasync16z(uint32_t dst, const void* src,
                                           bool valid) {
    int sz = valid ? 16 : 0;
    asm volatile("cp.async.cg.shared.global [%0], [%1], 16, %2;"
                 :: "r"(dst), "l"(src), "r"(sz));
}
#define CP_COMMIT() asm volatile("cp.async.commit_group;")
#define CP_WAIT(n)  asm volatile("cp.async.wait_group %0;" :: "n"(n))

__device__ __forceinline__ void ldsm4(uint32_t* r, uint32_t addr) {
    asm volatile("ldmatrix.sync.aligned.m8n8.x4.shared.b16 {%0,%1,%2,%3}, [%4];"
                 : "=r"(r[0]), "=r"(r[1]), "=r"(r[2]), "=r"(r[3])
                 : "r"(addr));
}

__device__ __forceinline__ void mma16n8k8(float* c, const uint32_t* a,
                                          uint32_t b0, uint32_t b1) {
    asm volatile(
        "mma.sync.aligned.m16n8k8.row.col.f32.tf32.tf32.f32 "
        "{%0,%1,%2,%3}, {%4,%5,%6,%7}, {%8,%9}, {%0,%1,%2,%3};\n"
        : "+f"(c[0]), "+f"(c[1]), "+f"(c[2]), "+f"(c[3])
        : "r"(a[0]), "r"(a[1]), "r"(a[2]), "r"(a[3]), "r"(b0), "r"(b1));
}

// ---------------------------------------------------------------------------
// Prep kernels
// ---------------------------------------------------------------------------
__global__ void round_copy_kernel(const float* __restrict__ src,
                                  float* __restrict__ dst, int n4) {
    int i = blockIdx.x * blockDim.x + threadIdx.x;
    if (i < n4) {
        float4 v = reinterpret_cast<const float4*>(src)[i];
        v.x = rn_tf32(v.x); v.y = rn_tf32(v.y);
        v.z = rn_tf32(v.z); v.w = rn_tf32(v.w);
        reinterpret_cast<float4*>(dst)[i] = v;
    }
}

__global__ void prep_adj_kernel(const float* __restrict__ adj,
                                const float* __restrict__ hw1,
                                const float* __restrict__ hw2) {
    int k = blockIdx.x * blockDim.x + threadIdx.x;   // 0..1023
    int c = blockIdx.y;                              // 0..999
    float a1 = 0.f, a2 = 0.f;
    if (k < C_DIM) {
        float av = adj[(size_t)c * C_DIM + k];
        float w1 = (hw1[k] + hw1[C_DIM + k] + hw1[2 * C_DIM + k]) * (1.f / 3.f);
        float w2 = (hw2[k] + hw2[C_DIM + k] + hw2[2 * C_DIM + k]) * (1.f / 3.f);
        a1 = rn_tf32(av * w1);
        a2 = rn_tf32(av * w2);
    }
    g_adj1[(size_t)c * CPAD + k] = a1;
    g_adj2[(size_t)c * CPAD + k] = a2;
}

// ---------------------------------------------------------------------------
// Fused tf32 mma.sync GEMM:  D[m,n] = sum_k A[m,k] * B[n,k]
//   MODE 0: +bias, round->Cout (ld CPAD)
//   MODE 1: relu, round->Cout  (ld CPAD)
//   MODE 2: Cout = resid + 0.5*acc (ld C_DIM, final output)
// lda = ldb = CPAD for all modes, K = CPAD.
// ---------------------------------------------------------------------------
__device__ __forceinline__ void load_tile(
    uint32_t sm0, const float* __restrict__ A, const float* __restrict__ Bm,
    int m0, int n0, int kt, int tid)
{
    const int slot = kt % STAGES;
    const uint32_t sA = sm0 + slot * STAGE_BYTES;
    const uint32_t sB = sA + TILE_FLOATS * 4;
    const int k0 = kt * BK;
    const int r  = tid >> 3;          // 0..31
    const int kl = (tid & 7) * 4;     // 0,4,...,28

#pragma unroll
    for (int p = 0; p < 4; p++) {
        const int row = p * 32 + r;
        cpasync16(sA + (uint32_t)(row * LDSTR + kl) * 4,
                  A + (size_t)(m0 + row) * CPAD + k0 + kl);
    }
#pragma unroll
    for (int p = 0; p < 4; p++) {
        const int row = p * 32 + r;
        const int n = n0 + row;
        const int nc = (n < C_DIM) ? n : (C_DIM - 1);   // clamp src addr
        cpasync16z(sB + (uint32_t)(row * LDSTR + kl) * 4,
                   Bm + (size_t)nc * CPAD + k0 + kl, n < C_DIM);
    }
}

template <int MODE>
__global__ void __launch_bounds__(NTH, 2)
gemm_tc(const float* __restrict__ A, const float* __restrict__ Bm,
        const float* __restrict__ bias, const float* __restrict__ resid,
        float* __restrict__ Cout)
{
    extern __shared__ float smem[];
    const uint32_t sm0 = su32(smem);

    const int tid  = threadIdx.x;
    const int warp = tid >> 5;
    const int lane = tid & 31;
    const int g = lane >> 2;          // groupID 0..7
    const int t = lane & 3;           // thread-in-group 0..3
    const int wm = (warp >> 2) * 64;  // warp M offset (0 or 64)
    const int wn = (warp & 3) * 32;   // warp N offset (0,32,64,96)

    const int m0 = blockIdx.y * BM;
    const int n0 = blockIdx.x * BN;

    // ldmatrix per-thread row addressing: matrix id = lane>>3, row = lane&7.
    const int mi  = lane >> 3;
    const int rid = lane & 7;
    // A x4 tiles: [m+0..7,k0..3][m+8..15,k0..3][m+0..7,k4..7][m+8..15,k4..7]
    const uint32_t aoff =
        (uint32_t)(((wm + (mi & 1) * 8 + rid) * LDSTR + (mi >> 1) * 4) * 4);
    // B x4 tiles: [n+0..7,k0..3][n+0..7,k4..7][n+8..15,k0..3][n+8..15,k4..7]
    const uint32_t boff = (uint32_t)(TILE_FLOATS * 4) +
        (uint32_t)(((wn + (mi >> 1) * 8 + rid) * LDSTR + (mi & 1) * 4) * 4);

    float acc[4][4][4];
#pragma unroll
    for (int i = 0; i < 4; i++)
#pragma unroll
        for (int j = 0; j < 4; j++)
#pragma unroll
            for (int c = 0; c < 4; c++) acc[i][j][c] = 0.f;

    // prologue: fill STAGES-1 stages
#pragma unroll
    for (int kt = 0; kt < STAGES - 1; kt++) {
        load_tile(sm0, A, Bm, m0, n0, kt, tid);
        CP_COMMIT();
    }

    for (int kt = 0; kt < KT; kt++) {
        CP_WAIT(STAGES - 2);
        __syncthreads();

        const int kn = kt + STAGES - 1;
        if (kn < KT) load_tile(sm0, A, Bm, m0, n0, kn, tid);
        CP_COMMIT();

        const int slot = kt % STAGES;
        const uint32_t sbase = sm0 + slot * STAGE_BYTES;

#pragma unroll
        for (int ks = 0; ks < 4; ks++) {
            const uint32_t kb = (uint32_t)(ks * 32);   // 8 floats = 32 bytes
            uint32_t a[4][4], b[2][4];
#pragma unroll
            for (int i = 0; i < 4; i++)
                ldsm4(a[i], sbase + aoff + (uint32_t)(i * 16 * LDSTR * 4) + kb);
#pragma unroll
            for (int jj = 0; jj < 2; jj++)
                ldsm4(b[jj], sbase + boff + (uint32_t)(jj * 16 * LDSTR * 4) + kb);
            // b[jj] regs: [n_lo k_lo][n_lo k_hi][n_hi k_lo][n_hi k_hi]
#pragma unroll
            for (int i = 0; i < 4; i++)
#pragma unroll
                for (int j = 0; j < 4; j++)
                    mma16n8k8(acc[i][j], a[i],
                              b[j >> 1][(j & 1) * 2], b[j >> 1][(j & 1) * 2 + 1]);
        }
    }

    // epilogue: per-thread float2 stores
#pragma unroll
    for (int i = 0; i < 4; i++) {
        const int mr0 = m0 + wm + i * 16 + g;       // rows mr0 and mr0+8
#pragma unroll
        for (int j = 0; j < 4; j++) {
            const int n = n0 + wn + j * 8 + t * 2;
            if (n < C_DIM) {
                float c0 = acc[i][j][0], c1 = acc[i][j][1];
                float c2 = acc[i][j][2], c3 = acc[i][j][3];
                if (MODE == 0) {
                    const float b0 = bias[n], b1 = bias[n + 1];
                    c0 = rn_tf32(c0 + b0); c1 = rn_tf32(c1 + b1);
                    c2 = rn_tf32(c2 + b0); c3 = rn_tf32(c3 + b1);
                } else if (MODE == 1) {
                    c0 = rn_tf32(fmaxf(c0, 0.f)); c1 = rn_tf32(fmaxf(c1, 0.f));
                    c2 = rn_tf32(fmaxf(c2, 0.f)); c3 = rn_tf32(fmaxf(c3, 0.f));
                }
                if (MODE == 2) {
                    float2 r0 = *reinterpret_cast<const float2*>(
                        resid + (size_t)mr0 * CPAD + n);
                    float2 r1 = *reinterpret_cast<const float2*>(
                        resid + (size_t)(mr0 + 8) * CPAD + n);
                    float2 v0 = make_float2(r0.x + 0.5f * c0, r0.y + 0.5f * c1);
                    float2 v1 = make_float2(r1.x + 0.5f * c2, r1.y + 0.5f * c3);
                    *reinterpret_cast<float2*>(
                        Cout + (size_t)mr0 * C_DIM + n) = v0;
                    *reinterpret_cast<float2*>(
                        Cout + (size_t)(mr0 + 8) * C_DIM + n) = v1;
                } else {
                    *reinterpret_cast<float2*>(
                        Cout + (size_t)mr0 * CPAD + n) = make_float2(c0, c1);
                    *reinterpret_cast<float2*>(
                        Cout + (size_t)(mr0 + 8) * CPAD + n) = make_float2(c2, c3);
                }
            }
        }
    }
}

// ---------------------------------------------------------------------------
// Launch: inputs per metadata order: x, adj, Wp, bp, hw1, hw2
// ---------------------------------------------------------------------------
extern "C" void kernel_launch(void* const* d_in, const int* in_sizes, int n_in,
                              void* d_out, int out_size) {
    const float* x   = (const float*)d_in[0];
    const float* adj = (const float*)d_in[1];
    const float* Wp  = (const float*)d_in[2];
    const float* bp  = (const float*)d_in[3];
    const float* hw1 = (const float*)d_in[4];
    const float* hw2 = (const float*)d_in[5];
    float* out = (float*)d_out;

    float *p_xrnd, *p_wp, *p_adj1, *p_adj2, *p_xinit, *p_out1;
    cudaGetSymbolAddress((void**)&p_xrnd,  g_xrnd);
    cudaGetSymbolAddress((void**)&p_wp,    g_wp);
    cudaGetSymbolAddress((void**)&p_adj1,  g_adj1);
    cudaGetSymbolAddress((void**)&p_adj2,  g_adj2);
    cudaGetSymbolAddress((void**)&p_xinit, g_xinit);
    cudaGetSymbolAddress((void**)&p_out1,  g_out1);

    cudaFuncSetAttribute(gemm_tc<0>,
        cudaFuncAttributeMaxDynamicSharedMemorySize, SMEM_BYTES);
    cudaFuncSetAttribute(gemm_tc<1>,
        cudaFuncAttributeMaxDynamicSharedMemorySize, SMEM_BYTES);
    cudaFuncSetAttribute(gemm_tc<2>,
        cudaFuncAttributeMaxDynamicSharedMemorySize, SMEM_BYTES);

    // prep: tf32-round x, Wp; prescale+round adj by head means
    {
        int n4 = (B_DIM * D_DIM) / 4;
        round_copy_kernel<<<(n4 + 255) / 256, 256>>>(x, p_xrnd, n4);
        int w4 = (C_DIM * D_DIM) / 4;
        round_copy_kernel<<<(w4 + 255) / 256, 256>>>(Wp, p_wp, w4);
        dim3 g(CPAD / 256, C_DIM);
        prep_adj_kernel<<<g, 256>>>(adj, hw1, hw2);
    }

    dim3 grid((C_DIM + BN - 1) / BN, B_DIM / BM);  // (8, 128)
    dim3 block(NTH);

    gemm_tc<0><<<grid, block, SMEM_BYTES>>>(p_xrnd, p_wp, bp, nullptr, p_xinit);
    gemm_tc<1><<<grid, block, SMEM_BYTES>>>(p_xinit, p_adj1, nullptr, nullptr, p_out1);
    gemm_tc<2><<<grid, block, SMEM_BYTES>>>(p_out1, p_adj2, nullptr, p_xinit, out);
}